// round 1
// baseline (speedup 1.0000x reference)
#include <cuda_runtime.h>
#include <math.h>

// ---------------- problem constants (fixed shapes for this problem) ----------
#define BB 32        // batch
#define CC 128       // channels
#define NN 16384     // H*W
#define KK 64        // clusters
#define TN 64        // n-tile per iteration
#define SPLITS 9     // split-K over n (32*9 = 288 CTAs ~ one wave at 2 CTA/SM)
#define NTILES (NN / TN)   // 256

// smem pitches (floats) chosen for bank-conflict control
#define WP 132
#define XP 68
#define AP 68

#define SMEM_FLOATS (KK*WP + CC*XP + KK*AP + 256 + 64)
#define SMEM_BYTES  (SMEM_FLOATS * 4)

// ---------------- deterministic scratch (no atomics anywhere) ----------------
__device__ float g_pv[(size_t)SPLITS * BB * KK * CC];  // partial vlad (9.4 MB)
__device__ float g_pa[SPLITS * BB * KK];               // partial softmax sums
__device__ float g_rss[BB * KK];                       // per-row sumsq after intra-norm

// ---------------- fast exp for v <= 0 (pure FFMA/ALU, no MUFU) ---------------
// rel err ~2.4e-6 (deg-5 Taylor of 2^f on [-0.5,0.5] + exponent splice)
__device__ __forceinline__ float fast_exp_neg(float v) {
    float t = v * 1.4426950408889634f;      // v*log2(e), t <= 0
    t = fmaxf(t, -30.0f);                    // exp(-20.8) ~ 1e-9, safe clamp
    float r  = t + 12582912.0f;              // round-to-nearest-int trick (1.5*2^23)
    float fi = r - 12582912.0f;
    float f  = t - fi;                       // f in [-0.5, 0.5]
    float p  = 0.0013333558146428443f;
    p = fmaf(p, f, 0.009618129107628477f);
    p = fmaf(p, f, 0.05550410866482158f);
    p = fmaf(p, f, 0.2402265069591007f);
    p = fmaf(p, f, 0.6931471805599453f);
    p = fmaf(p, f, 1.0f);                    // 2^f
    int ei = (int)fi;                        // in [-30, 0]
    return __int_as_float(__float_as_int(p) + (ei << 23));
}

#define F4(v, i) (((const float*)&(v))[i])

// ---------------- kernel 1: fused logits GEMM + softmax + VLAD GEMM ----------
__global__ __launch_bounds__(256, 2)
void nv_main_kernel(const float* __restrict__ x,
                    const float* __restrict__ conv_w,
                    const float* __restrict__ conv_b) {
    extern __shared__ float sm[];
    float* sW    = sm;                 // [KK][WP]
    float* sX    = sW + KK * WP;       // [CC][XP]
    float* sA    = sX + CC * XP;       // [KK][AP]  (logits -> softmax weights)
    float* sRed  = sA + KK * AP;       // [4][64]
    float* sBias = sRed + 256;         // [KK]

    const int tid = threadIdx.x;
    const int b   = blockIdx.y;
    const int s   = blockIdx.x;
    const int ty  = tid >> 4;          // 16 k-groups of 4
    const int tx  = tid & 15;          // 16 j-groups of 4 (phase1) / c-lanes (phase3)
    const int g   = tid >> 6;          // softmax k-quarter
    const int jj  = tid & 63;          // softmax column

    // load conv_w into smem with pitch WP (once)
    {
        const float4* w4 = (const float4*)conv_w;
        #pragma unroll
        for (int i = tid; i < KK * CC / 4; i += 256) {
            int k = i >> 5, c4 = i & 31;
            float4 v = w4[i];
            *(float4*)(sW + k * WP + (c4 << 2)) = v;
        }
        if (tid < KK) sBias[tid] = conv_b[tid];
    }

    // persistent accumulators
    float vacc[4][8];                  // vlad tile: k = 4*ty+i, c = tx + 16*i2
    #pragma unroll
    for (int i = 0; i < 4; i++)
        #pragma unroll
        for (int j = 0; j < 8; j++) vacc[i][j] = 0.0f;
    float apart[16];                   // per-thread partial of a.sum over n
    #pragma unroll
    for (int i = 0; i < 16; i++) apart[i] = 0.0f;

    const float* xb = x + (size_t)b * CC * NN;

    for (int t = s; t < NTILES; t += SPLITS) {
        const int n0 = t * TN;
        __syncthreads();   // protect sX/sA from previous iteration's readers

        // ---- load X tile: [CC][TN] floats, coalesced float4 ----
        #pragma unroll 4
        for (int i = tid; i < CC * TN / 4; i += 256) {
            int c = i >> 4, c4 = i & 15;
            float4 v = *(const float4*)(xb + (size_t)c * NN + n0 + (c4 << 2));
            *(float4*)(sX + c * XP + (c4 << 2)) = v;
        }
        __syncthreads();

        // ---- phase 1: L[64][64] = W @ Xtile + bias  (4k x 4j per thread) ----
        {
            float acc[4][4];
            #pragma unroll
            for (int i = 0; i < 4; i++) {
                float bi = sBias[4 * ty + i];
                #pragma unroll
                for (int j = 0; j < 4; j++) acc[i][j] = bi;
            }
            #pragma unroll 4
            for (int c = 0; c < CC; c += 4) {
                float4 wv[4], xv[4];
                #pragma unroll
                for (int i = 0; i < 4; i++)
                    wv[i] = *(const float4*)(sW + (4 * ty + i) * WP + c);
                #pragma unroll
                for (int i = 0; i < 4; i++)
                    xv[i] = *(const float4*)(sX + (c + i) * XP + (tx << 2));
                #pragma unroll
                for (int i = 0; i < 4; i++)
                    #pragma unroll
                    for (int i2 = 0; i2 < 4; i2++) {
                        float wf = F4(wv[i], i2);
                        acc[i][0] = fmaf(wf, xv[i2].x, acc[i][0]);
                        acc[i][1] = fmaf(wf, xv[i2].y, acc[i][1]);
                        acc[i][2] = fmaf(wf, xv[i2].z, acc[i][2]);
                        acc[i][3] = fmaf(wf, xv[i2].w, acc[i][3]);
                    }
            }
            #pragma unroll
            for (int i = 0; i < 4; i++) {
                float4 o = make_float4(acc[i][0], acc[i][1], acc[i][2], acc[i][3]);
                *(float4*)(sA + (4 * ty + i) * AP + (tx << 2)) = o;
            }
        }
        __syncthreads();

        // ---- phase 2: softmax(relu(L)) over K, column jj, rows g*16..g*16+15 ----
        {
            float l[16];
            float m = 0.0f;  // relu => values >= 0, so 0 is a valid max identity
            #pragma unroll
            for (int kk = 0; kk < 16; kk++) {
                float v = fmaxf(sA[(g * 16 + kk) * AP + jj], 0.0f);
                l[kk] = v;
                m = fmaxf(m, v);
            }
            sRed[g * 64 + jj] = m;
            __syncthreads();
            m = fmaxf(fmaxf(sRed[jj], sRed[64 + jj]),
                      fmaxf(sRed[128 + jj], sRed[192 + jj]));
            float e[16];
            float ss = 0.0f;
            #pragma unroll
            for (int kk = 0; kk < 16; kk++) {
                e[kk] = fast_exp_neg(l[kk] - m);
                ss += e[kk];
            }
            __syncthreads();            // everyone done reading maxes
            sRed[g * 64 + jj] = ss;
            __syncthreads();
            float tot = sRed[jj] + sRed[64 + jj] + sRed[128 + jj] + sRed[192 + jj];
            float rinv = 1.0f / tot;    // tot >= 1 (exp(0) term), safe
            #pragma unroll
            for (int kk = 0; kk < 16; kk++) {
                float a = e[kk] * rinv;
                sA[(g * 16 + kk) * AP + jj] = a;
                apart[kk] += a;
            }
        }
        __syncthreads();

        // ---- phase 3: vacc[k][c] += A[k][j] * X[c][j], j-vectorized by 4 ----
        {
            #pragma unroll 2
            for (int j = 0; j < TN; j += 4) {
                float4 av[4], xv[8];
                #pragma unroll
                for (int i = 0; i < 4; i++)
                    av[i] = *(const float4*)(sA + (4 * ty + i) * AP + j);
                #pragma unroll
                for (int i2 = 0; i2 < 8; i2++)
                    xv[i2] = *(const float4*)(sX + (tx + 16 * i2) * XP + j);
                #pragma unroll
                for (int i = 0; i < 4; i++)
                    #pragma unroll
                    for (int i2 = 0; i2 < 8; i2++) {
                        float acc = vacc[i][i2];
                        acc = fmaf(av[i].x, xv[i2].x, acc);
                        acc = fmaf(av[i].y, xv[i2].y, acc);
                        acc = fmaf(av[i].z, xv[i2].z, acc);
                        acc = fmaf(av[i].w, xv[i2].w, acc);
                        vacc[i][i2] = acc;
                    }
            }
        }
    }

    // ---- write partial vlad tile (deterministic split-K scratch) ----
    {
        float* pv = g_pv + ((size_t)(s * BB + b)) * KK * CC;
        #pragma unroll
        for (int i = 0; i < 4; i++)
            #pragma unroll
            for (int i2 = 0; i2 < 8; i2++)
                pv[(4 * ty + i) * CC + tx + 16 * i2] = vacc[i][i2];
    }

    // ---- reduce apart over columns via sA, write partial asum ----
    __syncthreads();
    #pragma unroll
    for (int kk = 0; kk < 16; kk++)
        sA[(g * 16 + kk) * AP + jj] = apart[kk];
    __syncthreads();
    if (tid < KK) {
        float ssum = 0.0f;
        #pragma unroll 8
        for (int j = 0; j < TN; j++) ssum += sA[tid * AP + j];
        g_pa[(s * BB + b) * KK + tid] = ssum;
    }
}

// ---------------- kernel 2: split-K reduce + centroid + intra-normalize ------
__global__ void nv_reduce_kernel(const float* __restrict__ centroids,
                                 float* __restrict__ out) {
    const int k = blockIdx.x, b = blockIdx.y, c = threadIdx.x;  // 128 threads
    float v = 0.0f;
    #pragma unroll
    for (int s = 0; s < SPLITS; s++)
        v += g_pv[(((size_t)s * BB + b) * KK + k) * CC + c];
    float as = 0.0f;
    #pragma unroll
    for (int s = 0; s < SPLITS; s++)
        as += g_pa[(s * BB + b) * KK + k];
    v -= as * centroids[k * CC + c];

    float ss = v * v;
    #pragma unroll
    for (int o = 16; o > 0; o >>= 1)
        ss += __shfl_xor_sync(0xffffffffu, ss, o);
    __shared__ float red[4];
    const int warp = c >> 5, lane = c & 31;
    if (lane == 0) red[warp] = ss;
    __syncthreads();
    float tot = red[0] + red[1] + red[2] + red[3];
    float inv = 1.0f / fmaxf(sqrtf(tot), 1e-12f);
    out[((size_t)b * KK + k) * CC + c] = v * inv;
    if (c == 0) g_rss[b * KK + k] = tot * inv * inv;
}

// ---------------- kernel 3: global L2 normalize per batch -------------------
__global__ void nv_gnorm_kernel(float* __restrict__ out) {
    const int b = blockIdx.y;
    __shared__ float ginv;
    if (threadIdx.x == 0) {
        float ss = 0.0f;
        #pragma unroll 8
        for (int k = 0; k < KK; k++) ss += g_rss[b * KK + k];
        ginv = 1.0f / fmaxf(sqrtf(ss), 1e-12f);
    }
    __syncthreads();
    int idx = b * KK * CC + blockIdx.x * 512 + threadIdx.x;
    out[idx] *= ginv;
}

// ---------------- launch -----------------------------------------------------
extern "C" void kernel_launch(void* const* d_in, const int* in_sizes, int n_in,
                              void* d_out, int out_size) {
    const float* x         = (const float*)d_in[0];  // (32,128,16384,1)
    const float* conv_w    = (const float*)d_in[1];  // (64,128)
    const float* conv_b    = (const float*)d_in[2];  // (64,)
    const float* centroids = (const float*)d_in[3];  // (64,128)
    float* out             = (float*)d_out;          // (32, 8192)

    cudaFuncSetAttribute((const void*)nv_main_kernel,
                         cudaFuncAttributeMaxDynamicSharedMemorySize, SMEM_BYTES);
    nv_main_kernel<<<dim3(SPLITS, BB), 256, SMEM_BYTES>>>(x, conv_w, conv_b);
    nv_reduce_kernel<<<dim3(KK, BB), 128>>>(centroids, out);
    nv_gnorm_kernel<<<dim3(16, BB), 512>>>(out);
}

// round 3
// speedup vs baseline: 1.4192x; 1.4192x over previous
#include <cuda_runtime.h>
#include <cuda_bf16.h>
#include <stdint.h>

// ---------------- problem constants ----------------
#define BB 32
#define CC 128
#define NN 16384
#define KK 64
#define TILE_N 128
#define STRIPES 4
#define NT ((NN / STRIPES) / TILE_N)   // 32 tiles per CTA

// ---------------- smem layout (bytes) ----------------
// bf16 tiles use pitch 136 elems (272 B = 17 x 16B, conflict-free ldmatrix)
#define PITCH   136
#define PB      272
#define OFF_XHI   0u          // x hi  [144 rows][136] bf16 (rows 128.. = ones/zeros)
#define OFF_XLO   39168u
#define OFF_WHI   78336u      // W hi  [64][136] bf16
#define OFF_WLO   95744u
#define OFF_AWHI  113152u     // softmax weights hi [64][136] bf16
#define OFF_AWLO  130560u
#define OFF_LOG   147968u     // logits fp32 [64][132]
#define PL        132
#define OFF_BIAS  181760u     // 64 fp32
#define OFF_RED   182016u     // 512 fp32 (max / sum exchange)
#define SMEM_BYTES 184064u

#define DXL 39168u   // hi->lo deltas
#define DWL 17408u
#define DAL 17408u

// ---------------- scratch (deterministic split-K, no atomics) ---------------
__device__ float g_pv[(size_t)STRIPES * BB * KK * CC];
__device__ float g_pa[STRIPES * BB * KK];
__device__ float g_rss[BB * KK];

// ---------------- helpers ----------------
__device__ __forceinline__ uint32_t smem_u32(const void* p) {
    uint32_t a;
    asm("{ .reg .u64 t; cvta.to.shared.u64 t, %1; cvt.u32.u64 %0, t; }"
        : "=r"(a) : "l"(p));
    return a;
}

__device__ __forceinline__ void ldm4(uint32_t* r, uint32_t a) {
    asm volatile("ldmatrix.sync.aligned.m8n8.x4.shared.b16 {%0,%1,%2,%3}, [%4];"
                 : "=r"(r[0]), "=r"(r[1]), "=r"(r[2]), "=r"(r[3]) : "r"(a));
}
__device__ __forceinline__ void ldm4t(uint32_t* r, uint32_t a) {
    asm volatile("ldmatrix.sync.aligned.m8n8.x4.trans.shared.b16 {%0,%1,%2,%3}, [%4];"
                 : "=r"(r[0]), "=r"(r[1]), "=r"(r[2]), "=r"(r[3]) : "r"(a));
}
__device__ __forceinline__ void mma_bf16(float* d, const uint32_t* a, const uint32_t* b2) {
    asm volatile("mma.sync.aligned.m16n8k16.row.col.f32.bf16.bf16.f32 "
                 "{%0,%1,%2,%3}, {%4,%5,%6,%7}, {%8,%9}, {%0,%1,%2,%3};"
                 : "+f"(d[0]), "+f"(d[1]), "+f"(d[2]), "+f"(d[3])
                 : "r"(a[0]), "r"(a[1]), "r"(a[2]), "r"(a[3]), "r"(b2[0]), "r"(b2[1]));
}

// fast exp for v <= 0: pure FFMA/ALU, rel err ~2.4e-6
__device__ __forceinline__ float fast_exp_neg(float v) {
    float t = v * 1.4426950408889634f;
    t = fmaxf(t, -30.0f);
    float r  = t + 12582912.0f;
    float fi = r - 12582912.0f;
    float f  = t - fi;
    float p  = 0.0013333558146428443f;
    p = fmaf(p, f, 0.009618129107628477f);
    p = fmaf(p, f, 0.05550410866482158f);
    p = fmaf(p, f, 0.2402265069591007f);
    p = fmaf(p, f, 0.6931471805599453f);
    p = fmaf(p, f, 1.0f);
    int ei = (int)fi;
    return __int_as_float(__float_as_int(p) + (ei << 23));
}

__device__ __forceinline__ void split_pack4(const float* f, uint32_t* hi, uint32_t* lo) {
    uint16_t h[4], l[4];
    #pragma unroll
    for (int j = 0; j < 4; ++j) {
        __nv_bfloat16 hb = __float2bfloat16(f[j]);
        h[j] = __bfloat16_as_ushort(hb);
        l[j] = __bfloat16_as_ushort(__float2bfloat16(f[j] - __bfloat162float(hb)));
    }
    hi[0] = (uint32_t)h[0] | ((uint32_t)h[1] << 16);
    hi[1] = (uint32_t)h[2] | ((uint32_t)h[3] << 16);
    lo[0] = (uint32_t)l[0] | ((uint32_t)l[1] << 16);
    lo[1] = (uint32_t)l[2] | ((uint32_t)l[3] << 16);
}

// ---------------- kernel 1: fused NetVLAD core via mma.sync bf16 ------------
__global__ __launch_bounds__(256, 1)
void nv_mma_kernel(const float* __restrict__ x,
                   const float* __restrict__ conv_w,
                   const float* __restrict__ conv_b) {
    extern __shared__ char sm[];
    const uint32_t sb = smem_u32(sm);
    float* smf = (float*)sm;
    const int tid = threadIdx.x;
    const int lane = tid & 31;
    const int w = tid >> 5;
    const int wm = w & 1;          // k-block (2 x 32)
    const int wn = w >> 1;         // n/c-block (4 x 32)
    const int b = blockIdx.y, stripe = blockIdx.x;

    // ---- W -> bf16 hi/lo (pitch 136) + bias ----
    #pragma unroll
    for (int it = 0; it < 8; ++it) {
        int i = it * 256 + tid;                 // 2048 float4
        int k = i >> 5, c4 = (i & 31) * 4;
        float4 v = ((const float4*)conv_w)[i];
        float f[4] = {v.x, v.y, v.z, v.w};
        uint32_t hi[2], lo[2];
        split_pack4(f, hi, lo);
        uint32_t off = (uint32_t)(k * PITCH + c4) * 2;
        *(uint2*)(sm + OFF_WHI + off) = make_uint2(hi[0], hi[1]);
        *(uint2*)(sm + OFF_WLO + off) = make_uint2(lo[0], lo[1]);
    }
    if (tid < KK) smf[(OFF_BIAS >> 2) + tid] = conv_b[tid];
    // constant x rows 128..135: row 128 = ones (asum trick), 129..135 zero
    if (tid < 128) {
        const uint16_t one = 0x3F80, zero = 0;
        *(uint16_t*)(sm + OFF_XHI + (128 * PITCH + tid) * 2) = one;
        *(uint16_t*)(sm + OFF_XLO + (128 * PITCH + tid) * 2) = zero;
        #pragma unroll
        for (int r = 129; r < 144; ++r) {
            *(uint16_t*)(sm + OFF_XHI + (r * PITCH + tid) * 2) = zero;
            *(uint16_t*)(sm + OFF_XLO + (r * PITCH + tid) * 2) = zero;
        }
    }
    __syncthreads();

    float accV[2][5][4];
    #pragma unroll
    for (int i = 0; i < 2; ++i)
        #pragma unroll
        for (int j = 0; j < 5; ++j)
            #pragma unroll
            for (int r = 0; r < 4; ++r) accV[i][j][r] = 0.0f;

    const float* xb = x + (size_t)b * CC * NN;
    const int nbase = stripe * (NN / STRIPES);

    // per-thread convert addressing
    const int cc = tid >> 1;
    const int noff = (tid & 1) * 64;
    const uint32_t dsthi = OFF_XHI + (uint32_t)(cc * PITCH + noff) * 2;
    const uint32_t dstlo = OFF_XLO + (uint32_t)(cc * PITCH + noff) * 2;

    // ldmatrix base addresses (lane-dependent parts precomputed)
    const uint32_t aA1 = sb + OFF_WHI + (uint32_t)((wm * 32 + (lane & 15)) * PB) +
                         (uint32_t)((lane >> 4) * 16);
    const uint32_t aB1 = sb + OFF_XHI + (uint32_t)((lane & 15) * PB) +
                         (uint32_t)((wn * 32 + ((lane >> 4) << 3)) * 2);
    const uint32_t aA2 = sb + OFF_AWHI + (uint32_t)((wm * 32 + (lane & 15)) * PB) +
                         (uint32_t)((lane >> 4) * 16);
    const uint32_t aB2 = sb + OFF_XHI +
                         (uint32_t)(((lane & 7) + ((lane >> 4) << 3)) * PB) +
                         (uint32_t)((lane & 8) * 2);

    const int g = tid >> 7;        // softmax k-half
    const int col = tid & 127;     // softmax column
    float* sRed = smf + (OFF_RED >> 2);
    float* sLog = smf + (OFF_LOG >> 2);
    float* sBias = smf + (OFF_BIAS >> 2);

    for (int tt = 0; tt < NT; ++tt) {
        __syncthreads();                      // smem tiles free for overwrite
        const int n0g = nbase + tt * TILE_N;

        // ---- convert: x fp32 -> bf16 hi/lo [c][n] ----
        {
            const float4* src = (const float4*)(xb + (size_t)cc * NN + n0g + noff);
            #pragma unroll
            for (int j = 0; j < 16; ++j) {
                float4 v = src[j];
                float f[4] = {v.x, v.y, v.z, v.w};
                uint32_t hi[2], lo[2];
                split_pack4(f, hi, lo);
                *(uint2*)(sm + dsthi + j * 8) = make_uint2(hi[0], hi[1]);
                *(uint2*)(sm + dstlo + j * 8) = make_uint2(lo[0], lo[1]);
            }
        }
        __syncthreads();

        // ---- GEMM1: logits[k][n] = W @ x  (3 bf16 products) ----
        {
            float accL[2][4][4];
            #pragma unroll
            for (int i = 0; i < 2; ++i)
                #pragma unroll
                for (int j = 0; j < 4; ++j)
                    #pragma unroll
                    for (int r = 0; r < 4; ++r) accL[i][j][r] = 0.0f;

            #pragma unroll
            for (int ks = 0; ks < 8; ++ks) {
                uint32_t Ahi[2][4], Alo[2][4], Bhi[2][4], Blo[2][4];
                #pragma unroll
                for (int mf = 0; mf < 2; ++mf) {
                    uint32_t a = aA1 + (uint32_t)(mf * 16 * PB + ks * 32);
                    ldm4(Ahi[mf], a);
                    ldm4(Alo[mf], a + DWL);
                }
                #pragma unroll
                for (int nfp = 0; nfp < 2; ++nfp) {
                    uint32_t a = aB1 + (uint32_t)(ks * 16 * PB + nfp * 32);
                    ldm4t(Bhi[nfp], a);
                    ldm4t(Blo[nfp], a + DXL);
                }
                #pragma unroll
                for (int mf = 0; mf < 2; ++mf)
                    #pragma unroll
                    for (int nfp = 0; nfp < 2; ++nfp)
                        #pragma unroll
                        for (int s = 0; s < 2; ++s) {
                            float* d = accL[mf][nfp * 2 + s];
                            mma_bf16(d, Ahi[mf], &Bhi[nfp][2 * s]);
                            mma_bf16(d, Ahi[mf], &Blo[nfp][2 * s]);
                            mma_bf16(d, Alo[mf], &Bhi[nfp][2 * s]);
                        }
            }
            // store logits fp32
            const int rowL = wm * 32 + (lane >> 2);
            const int colL = wn * 32 + 2 * (lane & 3);
            #pragma unroll
            for (int mf = 0; mf < 2; ++mf)
                #pragma unroll
                for (int nf = 0; nf < 4; ++nf) {
                    float* p = sLog + (rowL + mf * 16) * PL + colL + nf * 8;
                    *(float2*)p = make_float2(accL[mf][nf][0], accL[mf][nf][1]);
                    *(float2*)(p + 8 * PL) = make_float2(accL[mf][nf][2], accL[mf][nf][3]);
                }
        }
        __syncthreads();

        // ---- softmax(relu(logits + bias)) over k, column = col ----
        {
            float l[32];
            float mx = 0.0f;                       // relu floor
            #pragma unroll
            for (int i = 0; i < 32; ++i) {
                float lv = sLog[(g * 32 + i) * PL + col] + sBias[g * 32 + i];
                lv = fmaxf(lv, 0.0f);
                l[i] = lv;
                mx = fmaxf(mx, lv);
            }
            sRed[g * 128 + col] = mx;
            __syncthreads();
            mx = fmaxf(sRed[col], sRed[128 + col]);
            float ssum = 0.0f;
            #pragma unroll
            for (int i = 0; i < 32; ++i) {
                float e = fast_exp_neg(l[i] - mx);
                l[i] = e;
                ssum += e;
            }
            sRed[256 + g * 128 + col] = ssum;
            __syncthreads();
            float rinv = 1.0f / (sRed[256 + col] + sRed[384 + col]);
            #pragma unroll
            for (int i = 0; i < 32; ++i) {
                float a = l[i] * rinv;
                __nv_bfloat16 h = __float2bfloat16(a);
                float lo = a - __bfloat162float(h);
                uint32_t off = (uint32_t)((g * 32 + i) * PITCH + col) * 2;
                *(uint16_t*)(sm + OFF_AWHI + off) = __bfloat16_as_ushort(h);
                *(uint16_t*)(sm + OFF_AWLO + off) =
                    __bfloat16_as_ushort(__float2bfloat16(lo));
            }
        }
        __syncthreads();

        // ---- GEMM2: vlad[k][c] += aw @ x^T (+ asum via ones-row c=128) ----
        {
            #pragma unroll
            for (int ks = 0; ks < 8; ++ks) {
                uint32_t Ahi[2][4], Alo[2][4];
                #pragma unroll
                for (int mf = 0; mf < 2; ++mf) {
                    uint32_t a = aA2 + (uint32_t)(mf * 16 * PB + ks * 32);
                    ldm4(Ahi[mf], a);
                    ldm4(Alo[mf], a + DAL);
                }
                #pragma unroll
                for (int nfp = 0; nfp < 2; ++nfp) {
                    uint32_t a = aB2 + (uint32_t)((wn * 32 + nfp * 16) * PB + ks * 32);
                    uint32_t Bhi[4], Blo[4];
                    ldm4(Bhi, a);
                    ldm4(Blo, a + DXL);
                    #pragma unroll
                    for (int mf = 0; mf < 2; ++mf)
                        #pragma unroll
                        for (int s = 0; s < 2; ++s) {
                            float* d = accV[mf][nfp * 2 + s];
                            mma_bf16(d, Ahi[mf], &Bhi[2 * s]);
                            mma_bf16(d, Ahi[mf], &Blo[2 * s]);
                            mma_bf16(d, Alo[mf], &Bhi[2 * s]);
                        }
                }
                if (wn == 3) {                    // asum column (c = 128 ones row)
                    uint32_t a = aB2 + (uint32_t)(128 * PB + ks * 32);
                    uint32_t Bhi[4], Blo[4];
                    ldm4(Bhi, a);
                    ldm4(Blo, a + DXL);
                    #pragma unroll
                    for (int mf = 0; mf < 2; ++mf) {
                        float* d = accV[mf][4];
                        mma_bf16(d, Ahi[mf], &Bhi[0]);
                        mma_bf16(d, Ahi[mf], &Blo[0]);
                        mma_bf16(d, Alo[mf], &Bhi[0]);
                    }
                }
            }
        }
    }

    // ---- write partial vlad + asum ----
    {
        float* pv = g_pv + ((size_t)(stripe * BB + b)) * KK * CC;
        const int rowV = wm * 32 + (lane >> 2);
        const int colV = wn * 32 + 2 * (lane & 3);
        #pragma unroll
        for (int mf = 0; mf < 2; ++mf)
            #pragma unroll
            for (int nf = 0; nf < 4; ++nf) {
                int k = rowV + mf * 16, c = colV + nf * 8;
                *(float2*)&pv[k * CC + c] = make_float2(accV[mf][nf][0], accV[mf][nf][1]);
                *(float2*)&pv[(k + 8) * CC + c] = make_float2(accV[mf][nf][2], accV[mf][nf][3]);
            }
        if (wn == 3 && (lane & 3) == 0) {
            float* pa = g_pa + (stripe * BB + b) * KK;
            #pragma unroll
            for (int mf = 0; mf < 2; ++mf) {
                int k = wm * 32 + mf * 16 + (lane >> 2);
                pa[k] = accV[mf][4][0];
                pa[k + 8] = accV[mf][4][2];
            }
        }
    }
}

// ---------------- kernel 2: split-K reduce + centroid + intra-normalize -----
__global__ void nv_reduce_kernel(const float* __restrict__ centroids,
                                 float* __restrict__ out) {
    const int k = blockIdx.x, b = blockIdx.y, c = threadIdx.x;  // 128 threads
    float v = 0.0f;
    #pragma unroll
    for (int s = 0; s < STRIPES; s++)
        v += g_pv[(((size_t)s * BB + b) * KK + k) * CC + c];
    float as = 0.0f;
    #pragma unroll
    for (int s = 0; s < STRIPES; s++)
        as += g_pa[(s * BB + b) * KK + k];
    v -= as * centroids[k * CC + c];

    float ss = v * v;
    #pragma unroll
    for (int o = 16; o > 0; o >>= 1)
        ss += __shfl_xor_sync(0xffffffffu, ss, o);
    __shared__ float red[4];
    const int warp = c >> 5, lane = c & 31;
    if (lane == 0) red[warp] = ss;
    __syncthreads();
    float tot = red[0] + red[1] + red[2] + red[3];
    float inv = 1.0f / fmaxf(sqrtf(tot), 1e-12f);
    out[((size_t)b * KK + k) * CC + c] = v * inv;
    if (c == 0) g_rss[b * KK + k] = tot * inv * inv;
}

// ---------------- kernel 3: global L2 normalize per batch -------------------
__global__ void nv_gnorm_kernel(float* __restrict__ out) {
    const int b = blockIdx.y;
    __shared__ float ginv;
    if (threadIdx.x == 0) {
        float ss = 0.0f;
        #pragma unroll 8
        for (int k = 0; k < KK; k++) ss += g_rss[b * KK + k];
        ginv = 1.0f / fmaxf(sqrtf(ss), 1e-12f);
    }
    __syncthreads();
    int idx = b * KK * CC + blockIdx.x * 512 + threadIdx.x;
    out[idx] *= ginv;
}

// ---------------- launch -----------------------------------------------------
extern "C" void kernel_launch(void* const* d_in, const int* in_sizes, int n_in,
                              void* d_out, int out_size) {
    const float* x         = (const float*)d_in[0];  // (32,128,16384,1)
    const float* conv_w    = (const float*)d_in[1];  // (64,128)
    const float* conv_b    = (const float*)d_in[2];  // (64,)
    const float* centroids = (const float*)d_in[3];  // (64,128)
    float* out             = (float*)d_out;          // (32, 8192)

    cudaFuncSetAttribute((const void*)nv_mma_kernel,
                         cudaFuncAttributeMaxDynamicSharedMemorySize, SMEM_BYTES);
    nv_mma_kernel<<<dim3(STRIPES, BB), 256, SMEM_BYTES>>>(x, conv_w, conv_b);
    nv_reduce_kernel<<<dim3(KK, BB), 128>>>(centroids, out);
    nv_gnorm_kernel<<<dim3(16, BB), 512>>>(out);
}